// round 1
// baseline (speedup 1.0000x reference)
#include <cuda_runtime.h>
#include <cuda_bf16.h>
#include <cstdint>

#define B_ 16
#define V_ 40000
#define C_ 128
#define H_ 56
#define W_ 56
#define E_ 120000
#define HW_ (H_*W_)
#define BV_ (B_*V_)

// ---------------- scratch (device globals; no cudaMalloc allowed) ----------------
__device__ float g_featT[B_*HW_*C_];   // [B,H,W,C] transposed features (25.7MB)
__device__ float g_x[BV_*C_];          // g = vert_align + vertex_padded
__device__ float g_S[BV_*C_];          // neighbor-sum scratch
__device__ float g_d[BV_*C_];          // conv1 output (kept for final add)
__device__ float g_t[BV_*C_];          // conv2 output
__device__ int   g_deg[V_];
__device__ int   g_off[V_+1];
__device__ int   g_cur[V_];
__device__ int   g_adj[2*E_];

// ---------------- f32x2 helpers (FFMA2: 2x fp32 throughput, PTX-only) ----------------
__device__ __forceinline__ unsigned long long pack2(float lo, float hi){
    unsigned long long r;
    asm("mov.b64 %0, {%1, %2};" : "=l"(r) : "f"(lo), "f"(hi));
    return r;
}
__device__ __forceinline__ void ffma2(unsigned long long &acc, unsigned long long a, unsigned long long b){
    asm("fma.rn.f32x2 %0, %1, %2, %0;" : "+l"(acc) : "l"(a), "l"(b));
}
__device__ __forceinline__ float2 unpack2(unsigned long long v){
    float2 f;
    asm("mov.b64 {%0, %1}, %2;" : "=f"(f.x), "=f"(f.y) : "l"(v));
    return f;
}

// ---------------- 0) transpose [B,C,H,W] -> [B,H,W,C] ----------------
__global__ void transpose_kernel(const float* __restrict__ in, float* __restrict__ out){
    __shared__ float tile[32][33];
    int b = blockIdx.z;
    int hw0 = blockIdx.x*32, c0 = blockIdx.y*32;
    int tx = threadIdx.x, ty = threadIdx.y;
    #pragma unroll
    for (int k=0;k<4;k++){
        int c = c0 + ty + k*8;
        tile[ty+k*8][tx] = in[((size_t)(b*C_ + c))*HW_ + hw0 + tx];
    }
    __syncthreads();
    #pragma unroll
    for (int k=0;k<4;k++){
        int hw = hw0 + ty + k*8;
        out[((size_t)b*HW_ + hw)*C_ + c0 + tx] = tile[tx][ty+k*8];
    }
}

// ---------------- 1) vert_align + vertex_padded -> g_x ----------------
__global__ __launch_bounds__(256) void valign_kernel(
    const float* __restrict__ featT, const float* __restrict__ vpos,
    const float* __restrict__ vpad, float* __restrict__ g)
{
    int warp = blockIdx.x * 8 + (threadIdx.x >> 5);
    if (warp >= BV_) return;
    int lane = threadIdx.x & 31;
    int b = warp / V_;

    const float* vp = vpos + (size_t)warp*3;
    float fx = (vp[0] + 1.f) * 0.5f * (float)(W_-1);
    float fy = (vp[1] + 1.f) * 0.5f * (float)(H_-1);
    float x0f = floorf(fx), y0f = floorf(fy);
    float wx1 = fx - x0f, wx0 = 1.f - wx1;
    float wy1 = fy - y0f, wy0 = 1.f - wy1;
    int x0 = (int)x0f, y0 = (int)y0f;

    const float4* fb = (const float4*)featT + (size_t)b*HW_*32;
    float4 acc = make_float4(0.f,0.f,0.f,0.f);

    int xs[4] = {x0, x0+1, x0,   x0+1};
    int ys[4] = {y0, y0,   y0+1, y0+1};
    float wt[4] = {wx0*wy0, wx1*wy0, wx0*wy1, wx1*wy1};
    #pragma unroll
    for (int t=0;t<4;t++){
        int xi = xs[t], yi = ys[t];
        if (xi >= 0 && xi < W_ && yi >= 0 && yi < H_){
            float4 f = fb[(size_t)(yi*W_+xi)*32 + lane];
            float w = wt[t];
            acc.x += w*f.x; acc.y += w*f.y; acc.z += w*f.z; acc.w += w*f.w;
        }
    }
    float4 pv = ((const float4*)vpad)[(size_t)warp*32 + lane];
    acc.x += pv.x; acc.y += pv.y; acc.z += pv.z; acc.w += pv.w;
    ((float4*)g)[(size_t)warp*32 + lane] = acc;
}

// ---------------- 2) CSR build ----------------
__global__ void zero_deg_kernel(){
    int i = blockIdx.x*256 + threadIdx.x;
    if (i < V_) g_deg[i] = 0;
}
__global__ void count_deg_kernel(const int* __restrict__ edges){
    int e = blockIdx.x*256 + threadIdx.x;
    if (e < E_){
        int i = edges[2*e], j = edges[2*e+1];
        atomicAdd(&g_deg[i], 1);
        atomicAdd(&g_deg[j], 1);
    }
}
__global__ void scan_kernel(){
    __shared__ int wsum[32];
    __shared__ int s_carry;
    if (threadIdx.x == 0) s_carry = 0;
    __syncthreads();
    int lane = threadIdx.x & 31, w = threadIdx.x >> 5;
    for (int base = 0; base < V_; base += 1024){
        int i = base + (int)threadIdx.x;
        int v = (i < V_) ? g_deg[i] : 0;
        int x = v;
        #pragma unroll
        for (int d=1; d<32; d<<=1){ int y=__shfl_up_sync(0xffffffffu, x, d); if (lane>=d) x+=y; }
        if (lane == 31) wsum[w] = x;
        __syncthreads();
        if (w == 0){
            int s = wsum[lane];
            #pragma unroll
            for (int d=1; d<32; d<<=1){ int y=__shfl_up_sync(0xffffffffu, s, d); if (lane>=d) s+=y; }
            wsum[lane] = s;
        }
        __syncthreads();
        int incl = x + (w ? wsum[w-1] : 0) + s_carry;
        if (i < V_){ int ex = incl - v; g_off[i] = ex; g_cur[i] = ex; }
        __syncthreads();
        if (threadIdx.x == 1023) s_carry = incl;
        __syncthreads();
    }
    if (threadIdx.x == 0) g_off[V_] = s_carry;
}
__global__ void fill_adj_kernel(const int* __restrict__ edges){
    int e = blockIdx.x*256 + threadIdx.x;
    if (e < E_){
        int i = edges[2*e], j = edges[2*e+1];
        int p = atomicAdd(&g_cur[i], 1); g_adj[p] = j;
        int q = atomicAdd(&g_cur[j], 1); g_adj[q] = i;
    }
}

// ---------------- 3) neighbor sum: S[b,i,:] = sum_{j in adj(i)} x[b,j,:] ----------------
__global__ __launch_bounds__(256) void nsum_kernel(const float* __restrict__ x, float* __restrict__ S){
    int warp = blockIdx.x * 8 + (threadIdx.x >> 5);
    if (warp >= BV_) return;
    int lane = threadIdx.x & 31;
    int b = warp / V_, i = warp - b*V_;
    const float4* xb = (const float4*)(x + (size_t)b*V_*C_);
    float4 acc = make_float4(0.f,0.f,0.f,0.f);
    int p0 = g_off[i], p1 = g_off[i+1];
    for (int p = p0; p < p1; p++){
        int j = g_adj[p];
        float4 v = xb[(size_t)j*32 + lane];
        acc.x += v.x; acc.y += v.y; acc.z += v.z; acc.w += v.w;
    }
    ((float4*)(S + (size_t)b*V_*C_))[(size_t)i*32 + lane] = acc;
}

// ---------------- 4) fused GEMM: Y = X@Wa + S@Wb + bias (+ Z) ----------------
// 128x128 output tile per block, 256 threads, 8x8 micro-tile, K=256 (128 X + 128 S),
// fp32 accum via packed fma.rn.f32x2.
__global__ __launch_bounds__(256) void gemm_kernel(
    const float* __restrict__ X, const float* __restrict__ Sm,
    const float* __restrict__ Wa, const float* __restrict__ Wb,
    const float* __restrict__ bias, const float* __restrict__ Z,
    float* __restrict__ Y)
{
    __shared__ float xs[2][16][132];   // [k][row], padded row-stride (132) for STS conflicts
    __shared__ float ws[2][16][128];   // [k][col]
    const int tid = threadIdx.x;
    const long row0 = (long)blockIdx.x * 128;
    const int tr = (tid >> 4) * 4;     // rows tr..tr+3 and tr+64..tr+67
    const int tc = (tid & 15) * 4;     // cols tc..tc+3 and tc+64..tc+67

    unsigned long long acc[8][4];
    #pragma unroll
    for (int r=0;r<8;r++)
        #pragma unroll
        for (int c=0;c<4;c++) acc[r][c] = 0ull;

    float4 rx0, rx1, rw0, rw1;

    auto fetch = [&](int s){
        const float* M  = (s < 8) ? X  : Sm;
        const float* Wm = (s < 8) ? Wa : Wb;
        const int kx = (s & 7) * 16;
        {
            int idx = tid;
            int row = idx >> 2, q = idx & 3;
            rx0 = *(const float4*)(M + (row0+row)*128 + kx + q*4);
            int kr = idx >> 5, cq = idx & 31;
            rw0 = *(const float4*)(Wm + (size_t)(kx+kr)*128 + cq*4);
        }
        {
            int idx = tid + 256;
            int row = idx >> 2, q = idx & 3;
            rx1 = *(const float4*)(M + (row0+row)*128 + kx + q*4);
            int kr = idx >> 5, cq = idx & 31;
            rw1 = *(const float4*)(Wm + (size_t)(kx+kr)*128 + cq*4);
        }
    };
    auto store = [&](int buf){
        {
            int idx = tid;
            int row = idx >> 2, q = idx & 3;
            xs[buf][q*4+0][row] = rx0.x; xs[buf][q*4+1][row] = rx0.y;
            xs[buf][q*4+2][row] = rx0.z; xs[buf][q*4+3][row] = rx0.w;
            int kr = idx >> 5, cq = idx & 31;
            *(float4*)&ws[buf][kr][cq*4] = rw0;
        }
        {
            int idx = tid + 256;
            int row = idx >> 2, q = idx & 3;
            xs[buf][q*4+0][row] = rx1.x; xs[buf][q*4+1][row] = rx1.y;
            xs[buf][q*4+2][row] = rx1.z; xs[buf][q*4+3][row] = rx1.w;
            int kr = idx >> 5, cq = idx & 31;
            *(float4*)&ws[buf][kr][cq*4] = rw1;
        }
    };

    fetch(0); store(0);
    __syncthreads();

    #pragma unroll 1
    for (int s = 0; s < 16; s++){
        int buf = s & 1;
        if (s < 15) fetch(s+1);
        #pragma unroll
        for (int k = 0; k < 16; k++){
            float4 xa = *(const float4*)&xs[buf][k][tr];
            float4 xb = *(const float4*)&xs[buf][k][tr+64];
            float4 wa = *(const float4*)&ws[buf][k][tc];
            float4 wb = *(const float4*)&ws[buf][k][tc+64];
            unsigned long long wp0 = pack2(wa.x, wa.y);
            unsigned long long wp1 = pack2(wa.z, wa.w);
            unsigned long long wp2 = pack2(wb.x, wb.y);
            unsigned long long wp3 = pack2(wb.z, wb.w);
            float xr[8] = {xa.x,xa.y,xa.z,xa.w, xb.x,xb.y,xb.z,xb.w};
            #pragma unroll
            for (int r=0;r<8;r++){
                unsigned long long ad = pack2(xr[r], xr[r]);
                ffma2(acc[r][0], ad, wp0);
                ffma2(acc[r][1], ad, wp1);
                ffma2(acc[r][2], ad, wp2);
                ffma2(acc[r][3], ad, wp3);
            }
        }
        if (s < 15) store((s+1)&1);
        __syncthreads();
    }

    float4 ba = *(const float4*)(bias + tc);
    float4 bb = *(const float4*)(bias + tc + 64);
    #pragma unroll
    for (int r=0;r<8;r++){
        long row = row0 + tr + (r & 3) + ((r >> 2) * 64);
        float2 p0 = unpack2(acc[r][0]), p1 = unpack2(acc[r][1]);
        float2 p2 = unpack2(acc[r][2]), p3 = unpack2(acc[r][3]);
        float4 v0 = make_float4(p0.x + ba.x, p0.y + ba.y, p1.x + ba.z, p1.y + ba.w);
        float4 v1 = make_float4(p2.x + bb.x, p2.y + bb.y, p3.x + bb.z, p3.y + bb.w);
        if (Z){
            float4 z0 = *(const float4*)(Z + row*128 + tc);
            float4 z1 = *(const float4*)(Z + row*128 + tc + 64);
            v0.x += z0.x; v0.y += z0.y; v0.z += z0.z; v0.w += z0.w;
            v1.x += z1.x; v1.y += z1.y; v1.z += z1.z; v1.w += z1.w;
        }
        *(float4*)(Y + row*128 + tc)      = v0;
        *(float4*)(Y + row*128 + tc + 64) = v1;
    }
}

// ---------------- launch ----------------
extern "C" void kernel_launch(void* const* d_in, const int* in_sizes, int n_in,
                              void* d_out, int out_size)
{
    const float* img  = (const float*)d_in[0];
    const float* vpos = (const float*)d_in[1];
    const float* vpad = (const float*)d_in[2];
    const int*   edges= (const int*)  d_in[3];
    const float* w0_1 = (const float*)d_in[4];
    const float* b0_1 = (const float*)d_in[5];
    const float* w1_1 = (const float*)d_in[6];
    const float* w0_2 = (const float*)d_in[7];
    const float* b0_2 = (const float*)d_in[8];
    const float* w1_2 = (const float*)d_in[9];
    const float* w0_3 = (const float*)d_in[10];
    const float* b0_3 = (const float*)d_in[11];
    const float* w1_3 = (const float*)d_in[12];
    float* out = (float*)d_out;

    float *pft, *px, *ps, *pd, *pt;
    cudaGetSymbolAddress((void**)&pft, g_featT);
    cudaGetSymbolAddress((void**)&px,  g_x);
    cudaGetSymbolAddress((void**)&ps,  g_S);
    cudaGetSymbolAddress((void**)&pd,  g_d);
    cudaGetSymbolAddress((void**)&pt,  g_t);

    // features -> BHWC
    transpose_kernel<<<dim3(HW_/32, C_/32, B_), dim3(32,8)>>>(img, pft);
    // g = vert_align + vertex_padded
    valign_kernel<<<BV_/8, 256>>>(pft, vpos, vpad, px);
    // CSR adjacency
    zero_deg_kernel<<<(V_+255)/256, 256>>>();
    count_deg_kernel<<<(E_+255)/256, 256>>>(edges);
    scan_kernel<<<1, 1024>>>();
    fill_adj_kernel<<<(E_+255)/256, 256>>>(edges);

    // conv1: d = g@W0_1 + b0_1 + nsum(g)@W1_1
    nsum_kernel<<<BV_/8, 256>>>(px, ps);
    gemm_kernel<<<BV_/128, 256>>>(px, ps, w0_1, w1_1, b0_1, nullptr, pd);
    // conv2: t = d@W0_2 + b0_2 + nsum(d)@W1_2
    nsum_kernel<<<BV_/8, 256>>>(pd, ps);
    gemm_kernel<<<BV_/128, 256>>>(pd, ps, w0_2, w1_2, b0_2, nullptr, pt);
    // conv3 (+ fused final add of d): out = t@W0_3 + b0_3 + nsum(t)@W1_3 + d
    nsum_kernel<<<BV_/8, 256>>>(pt, ps);
    gemm_kernel<<<BV_/128, 256>>>(pt, ps, w0_3, w1_3, b0_3, pd, out);
}